// round 1
// baseline (speedup 1.0000x reference)
#include <cuda_runtime.h>

// Problem constants (fixed by the dataset)
#define NN 100000
#define EE 1600000
#define FF 128
#define GG 64
#define CC 3

// Scratch: __device__ globals (no allocation allowed)
__device__ int   g_deg[NN];
__device__ float g_dis[NN];
__device__ float g_h1[(size_t)NN * FF];   // GEMM output
__device__ float g_agg[(size_t)NN * FF];  // aggregation output
__device__ float g_sums[GG * FF];
__device__ float g_cnt[GG];

__device__ __forceinline__ void red_add_v4(float* addr, float x, float y, float z, float w) {
    asm volatile("red.global.add.v4.f32 [%0], {%1, %2, %3, %4};"
                 :: "l"(addr), "f"(x), "f"(y), "f"(z), "f"(w) : "memory");
}

// ---------------- init / degree / norm ----------------

__global__ void k_init() {
    int i = blockIdx.x * blockDim.x + threadIdx.x;
    if (i < NN) g_deg[i] = 1;             // self-loop
    if (i < GG * FF) g_sums[i] = 0.0f;
    if (i < GG) g_cnt[i] = 0.0f;
}

__global__ void k_count(const int* __restrict__ dst) {
    int e = blockIdx.x * blockDim.x + threadIdx.x;
    if (e < EE) atomicAdd(&g_deg[dst[e]], 1);
}

__global__ void k_dis() {
    int i = blockIdx.x * blockDim.x + threadIdx.x;
    if (i < NN) g_dis[i] = rsqrtf((float)g_deg[i]);
}

// ---------------- GEMM: h1 = act(A + bias) @ W ----------------
// BM=128, BN=128 (full width), BK=8, 256 threads, 8x8 thread tile.
// act fused on the A-load (bias indexed by input feature k).

__global__ __launch_bounds__(256) void k_gemm(
    const float* __restrict__ Aext, int useAgg,
    const float* __restrict__ W,
    const float* __restrict__ bias, int act,
    int nrows)
{
    __shared__ float As[8][128];
    __shared__ float Bs[8][128];

    const float* A = useAgg ? g_agg : Aext;
    int block_row = blockIdx.x * 128;
    int tid = threadIdx.x;
    int tx = tid & 15;        // 0..15 -> cols tx*8
    int ty = tid >> 4;        // 0..15 -> rows ty*8

    // A tile load: 128 rows x 8 k -> 256 float4 (1 per thread)
    int a_row  = tid >> 1;           // 0..127
    int a_col4 = (tid & 1) * 4;      // 0 or 4
    // B tile load: 8 k x 128 cols -> 256 float4
    int b_row = tid >> 5;            // 0..7
    int b_col = (tid & 31) * 4;      // 0..124

    float acc[8][8];
#pragma unroll
    for (int i = 0; i < 8; i++)
#pragma unroll
        for (int j = 0; j < 8; j++) acc[i][j] = 0.0f;

    for (int k0 = 0; k0 < FF; k0 += 8) {
        int gr = block_row + a_row;
        float4 av = make_float4(0.f, 0.f, 0.f, 0.f);
        if (gr < nrows)
            av = *(const float4*)(A + (size_t)gr * FF + k0 + a_col4);
        if (act) {
            av.x = fmaxf(av.x + bias[k0 + a_col4 + 0], 0.0f);
            av.y = fmaxf(av.y + bias[k0 + a_col4 + 1], 0.0f);
            av.z = fmaxf(av.z + bias[k0 + a_col4 + 2], 0.0f);
            av.w = fmaxf(av.w + bias[k0 + a_col4 + 3], 0.0f);
        }
        As[a_col4 + 0][a_row] = av.x;
        As[a_col4 + 1][a_row] = av.y;
        As[a_col4 + 2][a_row] = av.z;
        As[a_col4 + 3][a_row] = av.w;

        float4 bv = *(const float4*)(W + (size_t)(k0 + b_row) * FF + b_col);
        *(float4*)&Bs[b_row][b_col] = bv;
        __syncthreads();

#pragma unroll
        for (int k = 0; k < 8; k++) {
            float ar[8], br[8];
            *(float4*)&ar[0] = *(float4*)&As[k][ty * 8];
            *(float4*)&ar[4] = *(float4*)&As[k][ty * 8 + 4];
            *(float4*)&br[0] = *(float4*)&Bs[k][tx * 8];
            *(float4*)&br[4] = *(float4*)&Bs[k][tx * 8 + 4];
#pragma unroll
            for (int i = 0; i < 8; i++)
#pragma unroll
                for (int j = 0; j < 8; j++)
                    acc[i][j] = fmaf(ar[i], br[j], acc[i][j]);
        }
        __syncthreads();
    }

#pragma unroll
    for (int i = 0; i < 8; i++) {
        int gr = block_row + ty * 8 + i;
        if (gr < nrows) {
            float* dst = g_h1 + (size_t)gr * FF + tx * 8;
            *(float4*)(dst)     = make_float4(acc[i][0], acc[i][1], acc[i][2], acc[i][3]);
            *(float4*)(dst + 4) = make_float4(acc[i][4], acc[i][5], acc[i][6], acc[i][7]);
        }
    }
}

// ---------------- self-loop term (also initializes agg) ----------------
// agg[i] = dis[i]^2 * h1[i]   (one warp per node, float4 per lane)

__global__ void k_self() {
    int t = blockIdx.x * blockDim.x + threadIdx.x;
    int i = t >> 5, lane = t & 31;
    if (i >= NN) return;
    float d = g_dis[i];
    float c = d * d;
    const float4 v = *(const float4*)(g_h1 + (size_t)i * FF + lane * 4);
    float4 o = make_float4(v.x * c, v.y * c, v.z * c, v.w * c);
    *(float4*)(g_agg + (size_t)i * FF + lane * 4) = o;
}

// ---------------- edge scatter: agg[dst] += dis[src]*dis[dst]*h1[src] ----------------
// One warp per edge; 32 lanes x float4 = 128 features; vectorized L2 reductions.

__global__ void k_scatter(const int* __restrict__ src, const int* __restrict__ dst) {
    int t = blockIdx.x * blockDim.x + threadIdx.x;
    int e = t >> 5, lane = t & 31;
    if (e >= EE) return;
    int s = src[e], d = dst[e];
    float c = g_dis[s] * g_dis[d];
    const float4 v = *(const float4*)(g_h1 + (size_t)s * FF + lane * 4);
    red_add_v4(g_agg + (size_t)d * FF + lane * 4, v.x * c, v.y * c, v.z * c, v.w * c);
}

// ---------------- pooling: sums[batch[i]] += relu(agg[i] + b3) ----------------

__global__ void k_pool(const int* __restrict__ batch, const float* __restrict__ b3) {
    int t = blockIdx.x * blockDim.x + threadIdx.x;
    int i = t >> 5, lane = t & 31;
    if (i >= NN) return;
    int g = batch[i];
    float4 v = *(const float4*)(g_agg + (size_t)i * FF + lane * 4);
    float4 b = *(const float4*)(b3 + lane * 4);
    float x = fmaxf(v.x + b.x, 0.0f);
    float y = fmaxf(v.y + b.y, 0.0f);
    float z = fmaxf(v.z + b.z, 0.0f);
    float w = fmaxf(v.w + b.w, 0.0f);
    red_add_v4(g_sums + (size_t)g * FF + lane * 4, x, y, z, w);
    if (lane == 0) atomicAdd(&g_cnt[g], 1.0f);
}

// ---------------- head: out[g] = (sums[g]/cnt[g]) @ Wc + bc ----------------

__global__ void k_final(const float* __restrict__ Wc, const float* __restrict__ bc,
                        float* __restrict__ out) {
    __shared__ float r[CC][FF];
    int g = blockIdx.x;
    int t = threadIdx.x;  // 128 threads
    float p = g_sums[g * FF + t] / fmaxf(g_cnt[g], 1.0f);
    r[0][t] = p * Wc[t * CC + 0];
    r[1][t] = p * Wc[t * CC + 1];
    r[2][t] = p * Wc[t * CC + 2];
    __syncthreads();
    for (int s = 64; s > 0; s >>= 1) {
        if (t < s) {
            r[0][t] += r[0][t + s];
            r[1][t] += r[1][t + s];
            r[2][t] += r[2][t + s];
        }
        __syncthreads();
    }
    if (t < CC) out[g * CC + t] = r[t][0] + bc[t];
}

// ---------------- launch ----------------

extern "C" void kernel_launch(void* const* d_in, const int* in_sizes, int n_in,
                              void* d_out, int out_size) {
    const float* x     = (const float*)d_in[0];
    const int*   ei    = (const int*)d_in[1];   // [2, E] int32
    const int*   batch = (const int*)d_in[2];
    const float* W1    = (const float*)d_in[3];
    const float* b1    = (const float*)d_in[4];
    const float* W2    = (const float*)d_in[5];
    const float* b2    = (const float*)d_in[6];
    const float* W3    = (const float*)d_in[7];
    const float* b3    = (const float*)d_in[8];
    const float* Wc    = (const float*)d_in[9];
    const float* bc    = (const float*)d_in[10];
    float* out = (float*)d_out;

    const int* src = ei;
    const int* dst = ei + EE;

    const int T = 256;
    int nb_n  = (NN + T - 1) / T;
    int nb_e  = (EE + T - 1) / T;
    int nb_nw = ((size_t)NN * 32 + T - 1) / T;       // warp-per-node kernels
    int nb_ew = ((size_t)EE * 32 + T - 1) / T;       // warp-per-edge kernels
    int nb_g  = (NN + 127) / 128;                    // GEMM row blocks

    k_init<<<nb_n, T>>>();
    k_count<<<nb_e, T>>>(dst);
    k_dis<<<nb_n, T>>>();

    // Layer 1: h1 = x @ W1 ; agg1 = norm-aggregate(h1)   (bias b1 + relu deferred)
    k_gemm<<<nb_g, T>>>(x, 0, W1, nullptr, 0, NN);
    k_self<<<nb_nw, T>>>();
    k_scatter<<<nb_ew, T>>>(src, dst);

    // Layer 2: h1 = relu(agg1 + b1) @ W2 ; aggregate
    k_gemm<<<nb_g, T>>>(nullptr, 1, W2, b1, 1, NN);
    k_self<<<nb_nw, T>>>();
    k_scatter<<<nb_ew, T>>>(src, dst);

    // Layer 3: h1 = relu(agg2 + b2) @ W3 ; aggregate
    k_gemm<<<nb_g, T>>>(nullptr, 1, W3, b2, 1, NN);
    k_self<<<nb_nw, T>>>();
    k_scatter<<<nb_ew, T>>>(src, dst);

    // Pool (applies relu(agg3 + b3)) and classify
    k_pool<<<nb_nw, T>>>(batch, b3);
    k_final<<<GG, FF>>>(Wc, bc, out);
}

// round 2
// speedup vs baseline: 1.4762x; 1.4762x over previous
#include <cuda_runtime.h>

// Problem constants (fixed by the dataset)
#define NN 100000
#define EE 1600000
#define FF 128
#define GG 64
#define CC 3

#define SB 1024
#define NSB ((NN + SB - 1) / SB)   // 98

// Scratch: __device__ globals (no allocation allowed)
__device__ int   g_deg[NN];
__device__ float g_dis[NN];
__device__ float g_h1[(size_t)NN * FF];   // GEMM output
__device__ float g_agg[(size_t)NN * FF];  // aggregation output
__device__ float g_sums[GG * FF];
__device__ float g_cnt[GG];
__device__ int   g_rowoff[NN];
__device__ int   g_cursor[NN];
__device__ int   g_bsum[NSB];
__device__ int   g_csr_src[EE];
__device__ float g_csr_coef[EE];

__device__ __forceinline__ void red_add_v4(float* addr, float x, float y, float z, float w) {
    asm volatile("red.global.add.v4.f32 [%0], {%1, %2, %3, %4};"
                 :: "l"(addr), "f"(x), "f"(y), "f"(z), "f"(w) : "memory");
}

// ---------------- init / degree / norm ----------------

__global__ void k_init() {
    int i = blockIdx.x * blockDim.x + threadIdx.x;
    if (i < NN) g_deg[i] = 1;             // self-loop
    if (i < GG * FF) g_sums[i] = 0.0f;
    if (i < GG) g_cnt[i] = 0.0f;
}

__global__ void k_count(const int* __restrict__ dst) {
    int e = blockIdx.x * blockDim.x + threadIdx.x;
    if (e < EE) atomicAdd(&g_deg[dst[e]], 1);
}

__global__ void k_dis(const int* __restrict__ batch) {
    int i = blockIdx.x * blockDim.x + threadIdx.x;
    if (i < NN) {
        g_dis[i] = rsqrtf((float)g_deg[i]);
        atomicAdd(&g_cnt[batch[i]], 1.0f);
    }
}

// ---------------- CSR build: 2-level exclusive scan + binning ----------------

__global__ __launch_bounds__(SB) void k_bsum() {
    __shared__ int sh[SB];
    int i = blockIdx.x * SB + threadIdx.x;
    sh[threadIdx.x] = (i < NN) ? (g_deg[i] - 1) : 0;
    __syncthreads();
    for (int s = SB / 2; s > 0; s >>= 1) {
        if (threadIdx.x < s) sh[threadIdx.x] += sh[threadIdx.x + s];
        __syncthreads();
    }
    if (threadIdx.x == 0) g_bsum[blockIdx.x] = sh[0];
}

__global__ void k_scan_bsum() {
    if (threadIdx.x == 0) {
        int acc = 0;
        for (int b = 0; b < NSB; b++) { int t = g_bsum[b]; g_bsum[b] = acc; acc += t; }
    }
}

__global__ __launch_bounds__(SB) void k_rowoff() {
    __shared__ int sh[SB];
    int i = blockIdx.x * SB + threadIdx.x;
    int v = (i < NN) ? (g_deg[i] - 1) : 0;
    sh[threadIdx.x] = v;
    __syncthreads();
    for (int off = 1; off < SB; off <<= 1) {
        int t = (threadIdx.x >= off) ? sh[threadIdx.x - off] : 0;
        __syncthreads();
        sh[threadIdx.x] += t;
        __syncthreads();
    }
    if (i < NN) {
        g_rowoff[i] = g_bsum[blockIdx.x] + sh[threadIdx.x] - v;  // exclusive
        g_cursor[i] = 0;
    }
}

__global__ void k_bin(const int* __restrict__ src, const int* __restrict__ dst) {
    int e = blockIdx.x * blockDim.x + threadIdx.x;
    if (e >= EE) return;
    int s = src[e], d = dst[e];
    int pos = atomicAdd(&g_cursor[d], 1);
    int idx = g_rowoff[d] + pos;
    g_csr_src[idx] = s;
    g_csr_coef[idx] = g_dis[s] * g_dis[d];
}

// ---------------- GEMM: h1 = act(A + bias) @ W ----------------
// BM=128, BN=128 (full width), BK=8, 256 threads, 8x8 thread tile.
// act fused on the A-load (bias indexed by input feature k).

__global__ __launch_bounds__(256) void k_gemm(
    const float* __restrict__ Aext, int useAgg,
    const float* __restrict__ W,
    const float* __restrict__ bias, int act,
    int nrows)
{
    __shared__ float As[8][128];
    __shared__ float Bs[8][128];

    const float* A = useAgg ? g_agg : Aext;
    int block_row = blockIdx.x * 128;
    int tid = threadIdx.x;
    int tx = tid & 15;
    int ty = tid >> 4;

    int a_row  = tid >> 1;
    int a_col4 = (tid & 1) * 4;
    int b_row = tid >> 5;
    int b_col = (tid & 31) * 4;

    float acc[8][8];
#pragma unroll
    for (int i = 0; i < 8; i++)
#pragma unroll
        for (int j = 0; j < 8; j++) acc[i][j] = 0.0f;

    for (int k0 = 0; k0 < FF; k0 += 8) {
        int gr = block_row + a_row;
        float4 av = make_float4(0.f, 0.f, 0.f, 0.f);
        if (gr < nrows)
            av = *(const float4*)(A + (size_t)gr * FF + k0 + a_col4);
        if (act) {
            av.x = fmaxf(av.x + bias[k0 + a_col4 + 0], 0.0f);
            av.y = fmaxf(av.y + bias[k0 + a_col4 + 1], 0.0f);
            av.z = fmaxf(av.z + bias[k0 + a_col4 + 2], 0.0f);
            av.w = fmaxf(av.w + bias[k0 + a_col4 + 3], 0.0f);
        }
        As[a_col4 + 0][a_row] = av.x;
        As[a_col4 + 1][a_row] = av.y;
        As[a_col4 + 2][a_row] = av.z;
        As[a_col4 + 3][a_row] = av.w;

        float4 bv = *(const float4*)(W + (size_t)(k0 + b_row) * FF + b_col);
        *(float4*)&Bs[b_row][b_col] = bv;
        __syncthreads();

#pragma unroll
        for (int k = 0; k < 8; k++) {
            float ar[8], br[8];
            *(float4*)&ar[0] = *(float4*)&As[k][ty * 8];
            *(float4*)&ar[4] = *(float4*)&As[k][ty * 8 + 4];
            *(float4*)&br[0] = *(float4*)&Bs[k][tx * 8];
            *(float4*)&br[4] = *(float4*)&Bs[k][tx * 8 + 4];
#pragma unroll
            for (int i = 0; i < 8; i++)
#pragma unroll
                for (int j = 0; j < 8; j++)
                    acc[i][j] = fmaf(ar[i], br[j], acc[i][j]);
        }
        __syncthreads();
    }

#pragma unroll
    for (int i = 0; i < 8; i++) {
        int gr = block_row + ty * 8 + i;
        if (gr < nrows) {
            float* dst = g_h1 + (size_t)gr * FF + tx * 8;
            *(float4*)(dst)     = make_float4(acc[i][0], acc[i][1], acc[i][2], acc[i][3]);
            *(float4*)(dst + 4) = make_float4(acc[i][4], acc[i][5], acc[i][6], acc[i][7]);
        }
    }
}

// ---------------- CSR gather: agg[i] = dis[i]^2*h1[i] + sum_e coef_e * h1[src_e] ----
// One warp per node. Lanes cooperatively load 32 edges, broadcast via shuffle;
// each lane owns features [lane*4, lane*4+4). do_pool fuses relu(.+b3) + mean-pool
// reduction for the last layer (agg never materialized).

__global__ __launch_bounds__(256) void k_gather(
    const float* __restrict__ b3, const int* __restrict__ batch, int do_pool)
{
    int t = blockIdx.x * blockDim.x + threadIdx.x;
    int i = t >> 5, lane = t & 31;
    if (i >= NN) return;

    float di = g_dis[i];
    float c0 = di * di;
    const float4 hv = *(const float4*)(g_h1 + (size_t)i * FF + lane * 4);
    float4 acc = make_float4(hv.x * c0, hv.y * c0, hv.z * c0, hv.w * c0);

    int start = g_rowoff[i];
    int cnt   = g_deg[i] - 1;

    for (int j0 = 0; j0 < cnt; j0 += 32) {
        int myj = j0 + lane;
        int   s = 0;
        float c = 0.0f;
        if (myj < cnt) {
            s = g_csr_src[start + myj];
            c = g_csr_coef[start + myj];
        }
        int m = min(32, cnt - j0);
        for (int u = 0; u < m; u++) {
            int   ss = __shfl_sync(0xffffffffu, s, u);
            float cc = __shfl_sync(0xffffffffu, c, u);
            const float4 v = *(const float4*)(g_h1 + (size_t)ss * FF + lane * 4);
            acc.x = fmaf(cc, v.x, acc.x);
            acc.y = fmaf(cc, v.y, acc.y);
            acc.z = fmaf(cc, v.z, acc.z);
            acc.w = fmaf(cc, v.w, acc.w);
        }
    }

    if (do_pool) {
        const float4 b = *(const float4*)(b3 + lane * 4);
        float x = fmaxf(acc.x + b.x, 0.0f);
        float y = fmaxf(acc.y + b.y, 0.0f);
        float z = fmaxf(acc.z + b.z, 0.0f);
        float w = fmaxf(acc.w + b.w, 0.0f);
        int g = batch[i];
        red_add_v4(g_sums + (size_t)g * FF + lane * 4, x, y, z, w);
    } else {
        *(float4*)(g_agg + (size_t)i * FF + lane * 4) = acc;
    }
}

// ---------------- head: out[g] = (sums[g]/cnt[g]) @ Wc + bc ----------------

__global__ void k_final(const float* __restrict__ Wc, const float* __restrict__ bc,
                        float* __restrict__ out) {
    __shared__ float r[CC][FF];
    int g = blockIdx.x;
    int t = threadIdx.x;  // 128 threads
    float p = g_sums[g * FF + t] / fmaxf(g_cnt[g], 1.0f);
    r[0][t] = p * Wc[t * CC + 0];
    r[1][t] = p * Wc[t * CC + 1];
    r[2][t] = p * Wc[t * CC + 2];
    __syncthreads();
    for (int s = 64; s > 0; s >>= 1) {
        if (t < s) {
            r[0][t] += r[0][t + s];
            r[1][t] += r[1][t + s];
            r[2][t] += r[2][t + s];
        }
        __syncthreads();
    }
    if (t < CC) out[g * CC + t] = r[t][0] + bc[t];
}

// ---------------- launch ----------------

extern "C" void kernel_launch(void* const* d_in, const int* in_sizes, int n_in,
                              void* d_out, int out_size) {
    const float* x     = (const float*)d_in[0];
    const int*   ei    = (const int*)d_in[1];   // [2, E] int32
    const int*   batch = (const int*)d_in[2];
    const float* W1    = (const float*)d_in[3];
    const float* b1    = (const float*)d_in[4];
    const float* W2    = (const float*)d_in[5];
    const float* b2    = (const float*)d_in[6];
    const float* W3    = (const float*)d_in[7];
    const float* b3    = (const float*)d_in[8];
    const float* Wc    = (const float*)d_in[9];
    const float* bc    = (const float*)d_in[10];
    float* out = (float*)d_out;

    const int* src = ei;
    const int* dst = ei + EE;

    const int T = 256;
    int nb_n  = (NN + T - 1) / T;
    int nb_e  = (EE + T - 1) / T;
    int nb_nw = ((size_t)NN * 32 + T - 1) / T;       // warp-per-node kernels
    int nb_g  = (NN + 127) / 128;                    // GEMM row blocks

    // Graph preprocessing (once per launch)
    k_init<<<nb_n, T>>>();
    k_count<<<nb_e, T>>>(dst);
    k_dis<<<nb_n, T>>>(batch);
    k_bsum<<<NSB, SB>>>();
    k_scan_bsum<<<1, 32>>>();
    k_rowoff<<<NSB, SB>>>();
    k_bin<<<nb_e, T>>>(src, dst);

    // Layer 1: h1 = x @ W1 ; agg1 = normalized aggregate (b1+relu deferred)
    k_gemm<<<nb_g, T>>>(x, 0, W1, nullptr, 0, NN);
    k_gather<<<nb_nw, T>>>(nullptr, nullptr, 0);

    // Layer 2
    k_gemm<<<nb_g, T>>>(nullptr, 1, W2, b1, 1, NN);
    k_gather<<<nb_nw, T>>>(nullptr, nullptr, 0);

    // Layer 3 (gather fused with relu(.+b3) + mean-pool reduction)
    k_gemm<<<nb_g, T>>>(nullptr, 1, W3, b2, 1, NN);
    k_gather<<<nb_nw, T>>>(b3, batch, 1);

    // Classify
    k_final<<<GG, FF>>>(Wc, bc, out);
}